// round 15
// baseline (speedup 1.0000x reference)
#include <cuda_runtime.h>
#include <cuda_fp16.h>
#include <math.h>
#include <stdint.h>

// Problem constants
#define T_SEQ 2048
#define B_SZ  4
#define EMB   1024
#define NHEADS 16
#define HD    64
#define FFN_DIM 4096
#define MTOK  (T_SEQ * B_SZ)   // 8192 tokens
#define E3    (3 * EMB)

// ---------------- scratch (device globals; no cudaMalloc allowed) ----------
__device__ float  g_X0 [MTOK * EMB];
__device__ float  g_Y  [MTOK * EMB];
__device__ float  g_X1 [MTOK * EMB];
__device__ __half g_X0h[MTOK * EMB];
__device__ __half g_QKVh[MTOK * E3];
__device__ __half g_ATTNh[MTOK * EMB];
__device__ __half g_X1h[MTOK * EMB];
__device__ __half g_Hh [MTOK * FFN_DIM];
__device__ __half g_WQKVh[E3 * EMB];
__device__ float  g_BQKV [E3];
__device__ __half g_WOh[EMB * EMB];
__device__ __half g_W1h[FFN_DIM * EMB];
__device__ __half g_W2h[EMB * FFN_DIM];

// ---------------------------------------------------------------------------
__device__ __forceinline__ uint32_t smem_u32(const void* p) {
    uint32_t a;
    asm("{ .reg .u64 t; cvta.to.shared.u64 t, %1; cvt.u32.u64 %0, t; }" : "=r"(a) : "l"(p));
    return a;
}
__device__ __forceinline__ void mma_f16(float* d, const uint32_t* a, const uint32_t* b) {
    asm volatile(
        "mma.sync.aligned.m16n8k16.row.col.f32.f16.f16.f32 "
        "{%0,%1,%2,%3}, {%4,%5,%6,%7}, {%8,%9}, {%0,%1,%2,%3};"
        : "+f"(d[0]), "+f"(d[1]), "+f"(d[2]), "+f"(d[3])
        : "r"(a[0]), "r"(a[1]), "r"(a[2]), "r"(a[3]), "r"(b[0]), "r"(b[1]));
}
__device__ __forceinline__ void ldmx4t(uint32_t& r0, uint32_t& r1, uint32_t& r2, uint32_t& r3,
                                       uint32_t a) {
    asm volatile("ldmatrix.sync.aligned.m8n8.x4.trans.shared.b16 {%0,%1,%2,%3}, [%4];"
                 : "=r"(r0), "=r"(r1), "=r"(r2), "=r"(r3) : "r"(a));
}
__device__ __forceinline__ void cp_async16(uint32_t dst, const void* src) {
    asm volatile("cp.async.cg.shared.global [%0], [%1], 16;" :: "r"(dst), "l"(src));
}
__device__ __forceinline__ void cp_commit() { asm volatile("cp.async.commit_group;"); }
__device__ __forceinline__ float ex2(float x) {
    float r;
    asm("ex2.approx.f32 %0, %1;" : "=f"(r) : "f"(x));
    return r;
}

// ---------------------------------------------------------------------------
// Round ALL weights fp32 -> fp16 + concat QKV biases, one launch.
// ---------------------------------------------------------------------------
#define NW1 (EMB * EMB)
__global__ __launch_bounds__(256) void round_all_kernel(
    const float* __restrict__ q_w, const float* __restrict__ k_w,
    const float* __restrict__ v_w, const float* __restrict__ out_w,
    const float* __restrict__ fc1_w, const float* __restrict__ fc2_w,
    const float* __restrict__ q_b, const float* __restrict__ k_b,
    const float* __restrict__ v_b)
{
    int i = (blockIdx.x * 256 + threadIdx.x) * 4;
    if (i >= 12 * NW1) {
        int j = i - 12 * NW1;
        if (j < E3) {
            const float* s = (j < EMB) ? q_b : (j < 2 * EMB) ? k_b : v_b;
            *(float4*)(g_BQKV + j) = *(const float4*)(s + (j & (EMB - 1)));
        }
        return;
    }
    const float* src;
    __half* dst;
    int off;
    if (i < 3 * NW1) {
        dst = g_WQKVh + i;
        if (i < NW1)          { src = q_w; off = i; }
        else if (i < 2 * NW1) { src = k_w; off = i - NW1; }
        else                  { src = v_w; off = i - 2 * NW1; }
    } else if (i < 4 * NW1) { dst = g_WOh + (i - 3 * NW1); src = out_w; off = i - 3 * NW1; }
    else if (i < 8 * NW1)   { dst = g_W1h + (i - 4 * NW1); src = fc1_w; off = i - 4 * NW1; }
    else                    { dst = g_W2h + (i - 8 * NW1); src = fc2_w; off = i - 8 * NW1; }
    float4 v = *(const float4*)(src + off);
    __half2 h01 = __floats2half2_rn(v.x, v.y);
    __half2 h23 = __floats2half2_rn(v.z, v.w);
    uint2 u;
    u.x = *(uint32_t*)&h01;
    u.y = *(uint32_t*)&h23;
    *(uint2*)dst = u;
}

// ---------------------------------------------------------------------------
// fp16 tensor-core GEMM (mma.sync m16n8k16), 3-stage cp.async ring. (R10 best)
// ---------------------------------------------------------------------------
#define GPAD 36
#define STG_OP_UINTS (128 * GPAD)
#define STG_UINTS    (2 * STG_OP_UINTS)
#define GEMM_SMEM_BYTES (3 * STG_UINTS * 4)   // 110592

__global__ __launch_bounds__(256, 2) void gemm_f16_kernel(
    const __half* __restrict__ A, const __half* __restrict__ W,
    const float* __restrict__ bias, const float* __restrict__ res,
    float* __restrict__ Cf, __half* __restrict__ Ch,
    int M, int N, int K, int mode)
{
    extern __shared__ uint32_t smg[];
    const uint32_t sbase = smem_u32(smg);

    const int tid = threadIdx.x;
    const int wid = tid >> 5;
    const int lane = tid & 31;
    const int g   = lane >> 2;
    const int tig = lane & 3;
    const int wm = wid >> 2;
    const int wn = wid & 3;
    const int m0 = blockIdx.y * 128;
    const int n0 = blockIdx.x * 128;

    const __half* Ap = A + (size_t)m0 * K;
    const __half* Wp = W + (size_t)n0 * K;

    float acc[4][4][4];
#pragma unroll
    for (int mt = 0; mt < 4; mt++)
#pragma unroll
        for (int nt = 0; nt < 4; nt++)
#pragma unroll
            for (int e = 0; e < 4; e++) acc[mt][nt][e] = 0.f;

    const int S = K >> 6;

    auto issue_stage = [&](int s) {
        const int buf = s % 3;
        const int k0h = s << 6;
        const uint32_t abase = sbase + (uint32_t)(buf * STG_UINTS) * 4;
        const uint32_t bbase = abase + STG_OP_UINTS * 4;
#pragma unroll
        for (int i = 0; i < 4; i++) {
            int idx = tid + 256 * i;
            int row = idx >> 3, cu = (idx & 7) << 2;
            cp_async16(abase + (uint32_t)(row * GPAD + cu) * 4,
                       Ap + (size_t)row * K + k0h + cu * 2);
            cp_async16(bbase + (uint32_t)(row * GPAD + cu) * 4,
                       Wp + (size_t)row * K + k0h + cu * 2);
        }
        cp_commit();
    };

    issue_stage(0);
    issue_stage(1);

    for (int s = 0; s < S; s++) {
        asm volatile("cp.async.wait_group 1;" ::: "memory");
        __syncthreads();
        if (s + 2 < S) issue_stage(s + 2);
        else cp_commit();

        const int buf = s % 3;
        const uint32_t* Ab = smg + buf * STG_UINTS + (wm * 64) * GPAD;
        const uint32_t* Bb = smg + buf * STG_UINTS + STG_OP_UINTS + (wn * 32) * GPAD;
#pragma unroll
        for (int ks = 0; ks < 4; ks++) {
            uint32_t bf[4][2];
#pragma unroll
            for (int nt = 0; nt < 4; nt++) {
                const uint32_t* bp = Bb + (nt * 8 + g) * GPAD + ks * 8 + tig;
                bf[nt][0] = bp[0];
                bf[nt][1] = bp[4];
            }
#pragma unroll
            for (int mt = 0; mt < 4; mt++) {
                uint32_t af[4];
                const uint32_t* ap = Ab + (mt * 16 + g) * GPAD + ks * 8 + tig;
                af[0] = ap[0];
                af[1] = ap[8 * GPAD];
                af[2] = ap[4];
                af[3] = ap[8 * GPAD + 4];
#pragma unroll
                for (int nt = 0; nt < 4; nt++)
                    mma_f16(acc[mt][nt], af, bf[nt]);
            }
        }
    }

#pragma unroll
    for (int mt = 0; mt < 4; mt++) {
        int r0 = m0 + wm * 64 + mt * 16 + g;
#pragma unroll
        for (int half = 0; half < 2; half++) {
            int m = r0 + half * 8;
#pragma unroll
            for (int nt = 0; nt < 4; nt++) {
                int n = wn * 32 + nt * 8 + tig * 2;
                float ox = acc[mt][nt][half * 2 + 0] + bias[n0 + n + 0];
                float oy = acc[mt][nt][half * 2 + 1] + bias[n0 + n + 1];
                if (mode == 3) {
                    const float* Rrow = res + (size_t)m * N + n0;
                    float2 rr = *(const float2*)(Rrow + n);
                    *(float2*)(Cf + (size_t)m * N + n0 + n) = make_float2(ox + rr.x, oy + rr.y);
                } else {
                    if (mode == 2) { ox = fmaxf(ox, 0.f); oy = fmaxf(oy, 0.f); }
                    *(__half2*)(Ch + (size_t)m * N + n0 + n) = __floats2half2_rn(ox, oy);
                }
            }
        }
    }
}

// ---------------------------------------------------------------------------
// Transpose (T,B,E) -> (B,T,E): exact fp32 + fp16 copy
// ---------------------------------------------------------------------------
__global__ __launch_bounds__(256) void transpose_in_kernel(const float* __restrict__ state)
{
    int m = blockIdx.x;
    int b = m / T_SEQ;
    int t = m % T_SEQ;
    float4 v = ((const float4*)(state + (size_t)t * B_SZ * EMB + (size_t)b * EMB))[threadIdx.x];
    ((float4*)(g_X0 + (size_t)m * EMB))[threadIdx.x] = v;
    __half2 h01 = __floats2half2_rn(v.x, v.y);
    __half2 h23 = __floats2half2_rn(v.z, v.w);
    uint2 u;
    u.x = *(uint32_t*)&h01;
    u.y = *(uint32_t*)&h23;
    ((uint2*)(g_X0h + (size_t)m * EMB))[threadIdx.x] = u;
}

// ---------------------------------------------------------------------------
// Flash attention: fp16 mma, register-resident P, log2-domain softmax
// (scale folded into Q fill), ex2.approx, conditional alpha-rescale,
// 3-stage cp.async KV ring, one sync per kv-block.
// ---------------------------------------------------------------------------
#define APADU 36
#define AT_STAGE_UINTS (2 * 64 * APADU)
#define AT_SMEM_BYTES ((128 * APADU + 3 * AT_STAGE_UINTS) * 4)   // 73728
#define QSCALE_LOG2 (0.125f * 1.4426950408889634f)   // (1/sqrt(64)) * log2(e)

__global__ __launch_bounds__(256, 2) void attn_mma_kernel(const uint8_t* __restrict__ mask)
{
    extern __shared__ uint32_t sma[];
    uint32_t* Qs = sma;
    const uint32_t sbase = smem_u32(sma);

    const int tq = blockIdx.x * 128;
    const int b = blockIdx.y >> 4;
    const int h = blockIdx.y & 15;
    const int tid = threadIdx.x;
    const int w = tid >> 5;
    const int lane = tid & 31;
    const int g = lane >> 2;
    const int tig = lane & 3;

    // fill Q tile pre-scaled by 0.125*log2(e) -> scores land in exp2 domain
    {
        const __half* Qg = g_QKVh + (size_t)(b * T_SEQ + tq) * E3 + h * HD;
        for (int it = tid; it < 128 * 16; it += 256) {
            int r = it >> 4, c4 = (it & 15) * 4;
            uint2 raw = *(const uint2*)(Qg + (size_t)r * E3 + c4);
            float2 f0 = __half22float2(*(__half2*)&raw.x);
            float2 f1 = __half22float2(*(__half2*)&raw.y);
            __half2 h0 = __floats2half2_rn(f0.x * QSCALE_LOG2, f0.y * QSCALE_LOG2);
            __half2 h1 = __floats2half2_rn(f1.x * QSCALE_LOG2, f1.y * QSCALE_LOG2);
            uint32_t* d = Qs + r * APADU + (c4 >> 1);
            d[0] = *(uint32_t*)&h0;
            d[1] = *(uint32_t*)&h1;
        }
    }

    const __half* KgBase = g_QKVh + (size_t)(b * T_SEQ) * E3 + EMB + h * HD;
    const __half* VgBase = g_QKVh + (size_t)(b * T_SEQ) * E3 + 2 * EMB + h * HD;

    auto issue_kv = [&](int s) {
        const int buf = s % 3;
        const int kt = s << 6;
        const uint32_t kbase = sbase + (uint32_t)(128 * APADU + buf * AT_STAGE_UINTS) * 4;
        const uint32_t vbase = kbase + (uint32_t)(64 * APADU) * 4;
#pragma unroll
        for (int i = 0; i < 4; i++) {
            int idx = tid + 256 * i;
            int row = (idx >> 3) & 63;
            int chunk = idx & 7;
            int isV = idx >> 9;
            const __half* src = (isV ? VgBase : KgBase) + (size_t)(kt + row) * E3 + chunk * 8;
            uint32_t dst = (isV ? vbase : kbase) + (uint32_t)(row * APADU + chunk * 4) * 4;
            cp_async16(dst, src);
        }
        cp_commit();
    };

    issue_kv(0);
    issue_kv(1);
    __syncthreads();   // Qs visible

    uint32_t qf[4][4];
    {
        const uint32_t* base = Qs + (w * 16 + g) * APADU;
#pragma unroll
        for (int ks = 0; ks < 4; ks++) {
            qf[ks][0] = base[ks * 8 + tig];
            qf[ks][1] = base[8 * APADU + ks * 8 + tig];
            qf[ks][2] = base[ks * 8 + tig + 4];
            qf[ks][3] = base[8 * APADU + ks * 8 + tig + 4];
        }
    }

    float oacc[8][4];
#pragma unroll
    for (int nt = 0; nt < 8; nt++)
#pragma unroll
        for (int e = 0; e < 4; e++) oacc[nt][e] = 0.f;
    float mrow[2] = { -1e30f, -1e30f };
    float lrow[2] = { 0.f, 0.f };

    const uint8_t* mb = mask + (size_t)b * T_SEQ;
    const int NBLK = T_SEQ / 64;

    const int lm_quad = lane >> 3, lm_r = lane & 7;
    const int lm_row = (lm_quad & 1) * 8 + lm_r;
    const int lm_d   = (lm_quad >> 1) * 8;

    for (int s = 0; s < NBLK; s++) {
        asm volatile("cp.async.wait_group 1;" ::: "memory");
        __syncthreads();
        if (s + 2 < NBLK) issue_kv(s + 2);
        else cp_commit();

        const int buf = s % 3;
        const int kt = s << 6;
        const uint32_t* Ksb = sma + 128 * APADU + buf * AT_STAGE_UINTS;
        const uint32_t vsb_addr = sbase + (uint32_t)(128 * APADU + buf * AT_STAGE_UINTS + 64 * APADU) * 4;

        float sacc[8][4];
#pragma unroll
        for (int nt = 0; nt < 8; nt++)
#pragma unroll
            for (int e = 0; e < 4; e++) sacc[nt][e] = 0.f;

#pragma unroll
        for (int ks = 0; ks < 4; ks++) {
#pragma unroll
            for (int nt = 0; nt < 8; nt++) {
                uint32_t bf[2];
                const uint32_t* kp = Ksb + (nt * 8 + g) * APADU + ks * 8 + tig;
                bf[0] = kp[0];
                bf[1] = kp[4];
                mma_f16(sacc[nt], qf[ks], bf);
            }
        }

        // mask (pure select; scale already folded into Q)
#pragma unroll
        for (int nt = 0; nt < 8; nt++) {
            bool m0 = mb[kt + nt * 8 + 2 * tig] != 0;
            bool m1 = mb[kt + nt * 8 + 2 * tig + 1] != 0;
            if (m0) { sacc[nt][0] = -1e30f; sacc[nt][2] = -1e30f; }
            if (m1) { sacc[nt][1] = -1e30f; sacc[nt][3] = -1e30f; }
        }

        // online softmax in exp2 domain; P packed into sacc as half2 bits
#pragma unroll
        for (int half = 0; half < 2; half++) {
            float mx = -1e30f;
#pragma unroll
            for (int nt = 0; nt < 8; nt++) {
                mx = fmaxf(mx, sacc[nt][2 * half + 0]);
                mx = fmaxf(mx, sacc[nt][2 * half + 1]);
            }
            mx = fmaxf(mx, __shfl_xor_sync(0xffffffffu, mx, 1));
            mx = fmaxf(mx, __shfl_xor_sync(0xffffffffu, mx, 2));
            float mo = mrow[half];
            float mn = fmaxf(mo, mx);
            mrow[half] = mn;
            float rs = 0.f;
#pragma unroll
            for (int nt = 0; nt < 8; nt++) {
                float p0 = ex2(sacc[nt][2 * half + 0] - mn);
                float p1 = ex2(sacc[nt][2 * half + 1] - mn);
                rs += p0 + p1;
                __half2 ph = __floats2half2_rn(p0, p1);
                sacc[nt][2 * half] = __uint_as_float(*(uint32_t*)&ph);
            }
            rs += __shfl_xor_sync(0xffffffffu, rs, 1);
            rs += __shfl_xor_sync(0xffffffffu, rs, 2);
            if (mo < mn) {
                float alpha = ex2(mo - mn);
                lrow[half] = lrow[half] * alpha + rs;
#pragma unroll
                for (int nt = 0; nt < 8; nt++) {
                    oacc[nt][2 * half + 0] *= alpha;
                    oacc[nt][2 * half + 1] *= alpha;
                }
            } else {
                lrow[half] += rs;
            }
        }

        // O += P V : P from registers, V via ldmatrix.x4.trans
#pragma unroll
        for (int ks = 0; ks < 4; ks++) {
            uint32_t af[4];
            af[0] = __float_as_uint(sacc[2 * ks + 0][0]);
            af[1] = __float_as_uint(sacc[2 * ks + 0][2]);
            af[2] = __float_as_uint(sacc[2 * ks + 1][0]);
            af[3] = __float_as_uint(sacc[2 * ks + 1][2]);
#pragma unroll
            for (int np = 0; np < 4; np++) {
                int row = ks * 16 + lm_row;
                int d   = np * 16 + lm_d;
                uint32_t addr = vsb_addr + (uint32_t)(row * APADU + (d >> 1)) * 4;
                uint32_t r0, r1, r2, r3;
                ldmx4t(r0, r1, r2, r3, addr);
                uint32_t b0[2] = { r0, r1 };
                uint32_t b1[2] = { r2, r3 };
                mma_f16(oacc[2 * np + 0], af, b0);
                mma_f16(oacc[2 * np + 1], af, b1);
            }
        }
    }

#pragma unroll
    for (int half = 0; half < 2; half++) {
        float inv = 1.f / lrow[half];
        int r = tq + w * 16 + g + half * 8;
        __half* dst = g_ATTNh + (size_t)(b * T_SEQ + r) * EMB + h * HD;
#pragma unroll
        for (int nt = 0; nt < 8; nt++) {
            *(__half2*)(dst + nt * 8 + 2 * tig) =
                __floats2half2_rn(oacc[nt][2 * half + 0] * inv,
                                  oacc[nt][2 * half + 1] * inv);
        }
    }
}

// ---------------------------------------------------------------------------
// LayerNorm (E=1024), warp-shuffle reduction. Optional fp16 copy.
// ---------------------------------------------------------------------------
__global__ __launch_bounds__(256) void ln_kernel(
    const float* __restrict__ X, const float* __restrict__ gw,
    const float* __restrict__ bw, float* __restrict__ out,
    __half* __restrict__ out_h, int transposed)
{
    int m = blockIdx.x;
    float4 v = ((const float4*)(X + (size_t)m * EMB))[threadIdx.x];
    float s = v.x + v.y + v.z + v.w;
    float sq = v.x * v.x + v.y * v.y + v.z * v.z + v.w * v.w;

#pragma unroll
    for (int o = 16; o >= 1; o >>= 1) {
        s  += __shfl_xor_sync(0xffffffffu, s,  o);
        sq += __shfl_xor_sync(0xffffffffu, sq, o);
    }
    __shared__ float ws[8], wq[8];
    if ((threadIdx.x & 31) == 0) {
        ws[threadIdx.x >> 5] = s;
        wq[threadIdx.x >> 5] = sq;
    }
    __syncthreads();
    float ts = 0.f, tq = 0.f;
#pragma unroll
    for (int i = 0; i < 8; i++) { ts += ws[i]; tq += wq[i]; }

    float mu  = ts * (1.f / EMB);
    float var = tq * (1.f / EMB) - mu * mu;
    float inv = rsqrtf(var + 1e-5f);

    float4 g4 = ((const float4*)gw)[threadIdx.x];
    float4 b4 = ((const float4*)bw)[threadIdx.x];
    float4 o;
    o.x = (v.x - mu) * inv * g4.x + b4.x;
    o.y = (v.y - mu) * inv * g4.y + b4.y;
    o.z = (v.z - mu) * inv * g4.z + b4.z;
    o.w = (v.w - mu) * inv * g4.w + b4.w;

    size_t obase;
    if (transposed) {
        int b = m / T_SEQ, t = m % T_SEQ;
        obase = (size_t)t * B_SZ * EMB + (size_t)b * EMB;
    } else {
        obase = (size_t)m * EMB;
    }
    ((float4*)(out + obase))[threadIdx.x] = o;
    if (out_h) {
        __half2 h01 = __floats2half2_rn(o.x, o.y);
        __half2 h23 = __floats2half2_rn(o.z, o.w);
        uint2 u;
        u.x = *(uint32_t*)&h01;
        u.y = *(uint32_t*)&h23;
        ((uint2*)(out_h + (size_t)m * EMB))[threadIdx.x] = u;
    }
}

// ---------------------------------------------------------------------------
extern "C" void kernel_launch(void* const* d_in, const int* in_sizes, int n_in,
                              void* d_out, int out_size)
{
    const float*   state = (const float*)d_in[0];
    const uint8_t* mask  = (const uint8_t*)d_in[1];
    const float* q_w  = (const float*)d_in[2];
    const float* q_b  = (const float*)d_in[3];
    const float* k_w  = (const float*)d_in[4];
    const float* k_b  = (const float*)d_in[5];
    const float* v_w  = (const float*)d_in[6];
    const float* v_b  = (const float*)d_in[7];
    const float* out_w = (const float*)d_in[8];
    const float* out_b = (const float*)d_in[9];
    const float* ln1_g = (const float*)d_in[10];
    const float* ln1_b = (const float*)d_in[11];
    const float* fc1_w = (const float*)d_in[12];
    const float* fc1_b = (const float*)d_in[13];
    const float* fc2_w = (const float*)d_in[14];
    const float* fc2_b = (const float*)d_in[15];
    const float* ln2_g = (const float*)d_in[16];
    const float* ln2_b = (const float*)d_in[17];
    float* out = (float*)d_out;

    float *pX0, *pY, *pX1, *pBQKV;
    __half *pX0h, *pQKVh, *pATTNh, *pX1h, *pHh;
    __half *pWQKV, *pWO, *pW1, *pW2;
    cudaGetSymbolAddress((void**)&pX0,    g_X0);
    cudaGetSymbolAddress((void**)&pY,     g_Y);
    cudaGetSymbolAddress((void**)&pX1,    g_X1);
    cudaGetSymbolAddress((void**)&pX0h,   g_X0h);
    cudaGetSymbolAddress((void**)&pQKVh,  g_QKVh);
    cudaGetSymbolAddress((void**)&pATTNh, g_ATTNh);
    cudaGetSymbolAddress((void**)&pX1h,   g_X1h);
    cudaGetSymbolAddress((void**)&pHh,    g_Hh);
    cudaGetSymbolAddress((void**)&pWQKV,  g_WQKVh);
    cudaGetSymbolAddress((void**)&pBQKV,  g_BQKV);
    cudaGetSymbolAddress((void**)&pWO,    g_WOh);
    cudaGetSymbolAddress((void**)&pW1,    g_W1h);
    cudaGetSymbolAddress((void**)&pW2,    g_W2h);

    cudaFuncSetAttribute(attn_mma_kernel, cudaFuncAttributeMaxDynamicSharedMemorySize,
                         AT_SMEM_BYTES);
    cudaFuncSetAttribute(gemm_f16_kernel, cudaFuncAttributeMaxDynamicSharedMemorySize,
                         GEMM_SMEM_BYTES);

    // 0. prologue
    round_all_kernel<<<(12 * NW1 + E3) / 1024, 256>>>(q_w, k_w, v_w, out_w, fc1_w, fc2_w,
                                                      q_b, k_b, v_b);
    transpose_in_kernel<<<MTOK, 256>>>(state);

    // 1. fused QKV projection
    dim3 gQKV(E3 / 128, MTOK / 128);
    gemm_f16_kernel<<<gQKV, 256, GEMM_SMEM_BYTES>>>(pX0h, pWQKV, pBQKV, nullptr, nullptr, pQKVh, MTOK, E3, EMB, 0);

    // 2. attention
    dim3 gAttn(T_SEQ / 128, B_SZ * NHEADS);
    attn_mma_kernel<<<gAttn, 256, AT_SMEM_BYTES>>>(mask);

    // 3. out projection + residual(X0)
    dim3 gProj(EMB / 128, MTOK / 128);
    gemm_f16_kernel<<<gProj, 256, GEMM_SMEM_BYTES>>>(pATTNh, pWO, out_b, pX0, pY, nullptr, MTOK, EMB, EMB, 3);

    // 4. LN1
    ln_kernel<<<MTOK, 256>>>(pY, ln1_g, ln1_b, pX1, pX1h, 0);

    // 5. fc1 + relu
    dim3 gFc1(FFN_DIM / 128, MTOK / 128);
    gemm_f16_kernel<<<gFc1, 256, GEMM_SMEM_BYTES>>>(pX1h, pW1, fc1_b, nullptr, nullptr, pHh, MTOK, FFN_DIM, EMB, 2);

    // 6. fc2 + residual(X1)
    gemm_f16_kernel<<<gProj, 256, GEMM_SMEM_BYTES>>>(pHh, pW2, fc2_b, pX1, pY, nullptr, MTOK, EMB, FFN_DIM, 3);

    // 7. LN2 -> output (T,B,E)
    ln_kernel<<<MTOK, 256>>>(pY, ln2_g, ln2_b, out, nullptr, 1);
}

// round 16
// speedup vs baseline: 1.0283x; 1.0283x over previous
#include <cuda_runtime.h>
#include <cuda_fp16.h>
#include <math.h>
#include <stdint.h>

// Problem constants
#define T_SEQ 2048
#define B_SZ  4
#define EMB   1024
#define NHEADS 16
#define HD    64
#define FFN_DIM 4096
#define MTOK  (T_SEQ * B_SZ)   // 8192 tokens
#define E3    (3 * EMB)

// ---------------- scratch (device globals; no cudaMalloc allowed) ----------
__device__ float  g_X0 [MTOK * EMB];
__device__ float  g_Y  [MTOK * EMB];
__device__ float  g_X1 [MTOK * EMB];
__device__ __half g_X0h[MTOK * EMB];
__device__ __half g_QKVh[MTOK * E3];
__device__ __half g_ATTNh[MTOK * EMB];
__device__ __half g_X1h[MTOK * EMB];
__device__ __half g_Hh [MTOK * FFN_DIM];
__device__ __half g_WQKVh[E3 * EMB];
__device__ float  g_BQKV [E3];
__device__ __half g_WOh[EMB * EMB];
__device__ __half g_W1h[FFN_DIM * EMB];
__device__ __half g_W2h[EMB * FFN_DIM];

// ---------------------------------------------------------------------------
__device__ __forceinline__ uint32_t smem_u32(const void* p) {
    uint32_t a;
    asm("{ .reg .u64 t; cvta.to.shared.u64 t, %1; cvt.u32.u64 %0, t; }" : "=r"(a) : "l"(p));
    return a;
}
__device__ __forceinline__ void mma_f16(float* d, const uint32_t* a, const uint32_t* b) {
    asm volatile(
        "mma.sync.aligned.m16n8k16.row.col.f32.f16.f16.f32 "
        "{%0,%1,%2,%3}, {%4,%5,%6,%7}, {%8,%9}, {%0,%1,%2,%3};"
        : "+f"(d[0]), "+f"(d[1]), "+f"(d[2]), "+f"(d[3])
        : "r"(a[0]), "r"(a[1]), "r"(a[2]), "r"(a[3]), "r"(b[0]), "r"(b[1]));
}
__device__ __forceinline__ void ldmx4t(uint32_t& r0, uint32_t& r1, uint32_t& r2, uint32_t& r3,
                                       uint32_t a) {
    asm volatile("ldmatrix.sync.aligned.m8n8.x4.trans.shared.b16 {%0,%1,%2,%3}, [%4];"
                 : "=r"(r0), "=r"(r1), "=r"(r2), "=r"(r3) : "r"(a));
}
__device__ __forceinline__ void cp_async16(uint32_t dst, const void* src) {
    asm volatile("cp.async.cg.shared.global [%0], [%1], 16;" :: "r"(dst), "l"(src));
}
__device__ __forceinline__ void cp_commit() { asm volatile("cp.async.commit_group;"); }
__device__ __forceinline__ float ex2(float x) {
    float r;
    asm("ex2.approx.f32 %0, %1;" : "=f"(r) : "f"(x));
    return r;
}

// ---------------------------------------------------------------------------
// Round ALL weights fp32 -> fp16 + concat QKV biases, one launch.
// ---------------------------------------------------------------------------
#define NW1 (EMB * EMB)
__global__ __launch_bounds__(256) void round_all_kernel(
    const float* __restrict__ q_w, const float* __restrict__ k_w,
    const float* __restrict__ v_w, const float* __restrict__ out_w,
    const float* __restrict__ fc1_w, const float* __restrict__ fc2_w,
    const float* __restrict__ q_b, const float* __restrict__ k_b,
    const float* __restrict__ v_b)
{
    int i = (blockIdx.x * 256 + threadIdx.x) * 4;
    if (i >= 12 * NW1) {
        int j = i - 12 * NW1;
        if (j < E3) {
            const float* s = (j < EMB) ? q_b : (j < 2 * EMB) ? k_b : v_b;
            *(float4*)(g_BQKV + j) = *(const float4*)(s + (j & (EMB - 1)));
        }
        return;
    }
    const float* src;
    __half* dst;
    int off;
    if (i < 3 * NW1) {
        dst = g_WQKVh + i;
        if (i < NW1)          { src = q_w; off = i; }
        else if (i < 2 * NW1) { src = k_w; off = i - NW1; }
        else                  { src = v_w; off = i - 2 * NW1; }
    } else if (i < 4 * NW1) { dst = g_WOh + (i - 3 * NW1); src = out_w; off = i - 3 * NW1; }
    else if (i < 8 * NW1)   { dst = g_W1h + (i - 4 * NW1); src = fc1_w; off = i - 4 * NW1; }
    else                    { dst = g_W2h + (i - 8 * NW1); src = fc2_w; off = i - 8 * NW1; }
    float4 v = *(const float4*)(src + off);
    __half2 h01 = __floats2half2_rn(v.x, v.y);
    __half2 h23 = __floats2half2_rn(v.z, v.w);
    uint2 u;
    u.x = *(uint32_t*)&h01;
    u.y = *(uint32_t*)&h23;
    *(uint2*)dst = u;
}

// ---------------------------------------------------------------------------
// fp16 tensor-core GEMM (mma.sync m16n8k16), 3-stage cp.async ring. (R10 best)
// ---------------------------------------------------------------------------
#define GPAD 36
#define STG_OP_UINTS (128 * GPAD)
#define STG_UINTS    (2 * STG_OP_UINTS)
#define GEMM_SMEM_BYTES (3 * STG_UINTS * 4)   // 110592

__global__ __launch_bounds__(256, 2) void gemm_f16_kernel(
    const __half* __restrict__ A, const __half* __restrict__ W,
    const float* __restrict__ bias, const float* __restrict__ res,
    float* __restrict__ Cf, __half* __restrict__ Ch,
    int M, int N, int K, int mode)
{
    extern __shared__ uint32_t smg[];
    const uint32_t sbase = smem_u32(smg);

    const int tid = threadIdx.x;
    const int wid = tid >> 5;
    const int lane = tid & 31;
    const int g   = lane >> 2;
    const int tig = lane & 3;
    const int wm = wid >> 2;
    const int wn = wid & 3;
    const int m0 = blockIdx.y * 128;
    const int n0 = blockIdx.x * 128;

    const __half* Ap = A + (size_t)m0 * K;
    const __half* Wp = W + (size_t)n0 * K;

    float acc[4][4][4];
#pragma unroll
    for (int mt = 0; mt < 4; mt++)
#pragma unroll
        for (int nt = 0; nt < 4; nt++)
#pragma unroll
            for (int e = 0; e < 4; e++) acc[mt][nt][e] = 0.f;

    const int S = K >> 6;

    auto issue_stage = [&](int s) {
        const int buf = s % 3;
        const int k0h = s << 6;
        const uint32_t abase = sbase + (uint32_t)(buf * STG_UINTS) * 4;
        const uint32_t bbase = abase + STG_OP_UINTS * 4;
#pragma unroll
        for (int i = 0; i < 4; i++) {
            int idx = tid + 256 * i;
            int row = idx >> 3, cu = (idx & 7) << 2;
            cp_async16(abase + (uint32_t)(row * GPAD + cu) * 4,
                       Ap + (size_t)row * K + k0h + cu * 2);
            cp_async16(bbase + (uint32_t)(row * GPAD + cu) * 4,
                       Wp + (size_t)row * K + k0h + cu * 2);
        }
        cp_commit();
    };

    issue_stage(0);
    issue_stage(1);

    for (int s = 0; s < S; s++) {
        asm volatile("cp.async.wait_group 1;" ::: "memory");
        __syncthreads();
        if (s + 2 < S) issue_stage(s + 2);
        else cp_commit();

        const int buf = s % 3;
        const uint32_t* Ab = smg + buf * STG_UINTS + (wm * 64) * GPAD;
        const uint32_t* Bb = smg + buf * STG_UINTS + STG_OP_UINTS + (wn * 32) * GPAD;
#pragma unroll
        for (int ks = 0; ks < 4; ks++) {
            uint32_t bf[4][2];
#pragma unroll
            for (int nt = 0; nt < 4; nt++) {
                const uint32_t* bp = Bb + (nt * 8 + g) * GPAD + ks * 8 + tig;
                bf[nt][0] = bp[0];
                bf[nt][1] = bp[4];
            }
#pragma unroll
            for (int mt = 0; mt < 4; mt++) {
                uint32_t af[4];
                const uint32_t* ap = Ab + (mt * 16 + g) * GPAD + ks * 8 + tig;
                af[0] = ap[0];
                af[1] = ap[8 * GPAD];
                af[2] = ap[4];
                af[3] = ap[8 * GPAD + 4];
#pragma unroll
                for (int nt = 0; nt < 4; nt++)
                    mma_f16(acc[mt][nt], af, bf[nt]);
            }
        }
    }

#pragma unroll
    for (int mt = 0; mt < 4; mt++) {
        int r0 = m0 + wm * 64 + mt * 16 + g;
#pragma unroll
        for (int half = 0; half < 2; half++) {
            int m = r0 + half * 8;
#pragma unroll
            for (int nt = 0; nt < 4; nt++) {
                int n = wn * 32 + nt * 8 + tig * 2;
                float ox = acc[mt][nt][half * 2 + 0] + bias[n0 + n + 0];
                float oy = acc[mt][nt][half * 2 + 1] + bias[n0 + n + 1];
                if (mode == 3) {
                    const float* Rrow = res + (size_t)m * N + n0;
                    float2 rr = *(const float2*)(Rrow + n);
                    *(float2*)(Cf + (size_t)m * N + n0 + n) = make_float2(ox + rr.x, oy + rr.y);
                } else {
                    if (mode == 2) { ox = fmaxf(ox, 0.f); oy = fmaxf(oy, 0.f); }
                    *(__half2*)(Ch + (size_t)m * N + n0 + n) = __floats2half2_rn(ox, oy);
                }
            }
        }
    }
}

// ---------------------------------------------------------------------------
// Transpose (T,B,E) -> (B,T,E): exact fp32 + fp16 copy
// ---------------------------------------------------------------------------
__global__ __launch_bounds__(256) void transpose_in_kernel(const float* __restrict__ state)
{
    int m = blockIdx.x;
    int b = m / T_SEQ;
    int t = m % T_SEQ;
    float4 v = ((const float4*)(state + (size_t)t * B_SZ * EMB + (size_t)b * EMB))[threadIdx.x];
    ((float4*)(g_X0 + (size_t)m * EMB))[threadIdx.x] = v;
    __half2 h01 = __floats2half2_rn(v.x, v.y);
    __half2 h23 = __floats2half2_rn(v.z, v.w);
    uint2 u;
    u.x = *(uint32_t*)&h01;
    u.y = *(uint32_t*)&h23;
    ((uint2*)(g_X0h + (size_t)m * EMB))[threadIdx.x] = u;
}

// ---------------------------------------------------------------------------
// Flash attention: fp16 mma, register-resident P, log2-domain softmax
// (scale folded into Q), ex2.approx, BRANCHLESS alpha-rescale (R11 structure),
// 3-stage cp.async KV ring, one sync per kv-block.
// ---------------------------------------------------------------------------
#define APADU 36
#define AT_STAGE_UINTS (2 * 64 * APADU)
#define AT_SMEM_BYTES ((128 * APADU + 3 * AT_STAGE_UINTS) * 4)   // 73728
#define QSCALE_LOG2 (0.125f * 1.4426950408889634f)   // (1/sqrt(64)) * log2(e)

__global__ __launch_bounds__(256, 2) void attn_mma_kernel(const uint8_t* __restrict__ mask)
{
    extern __shared__ uint32_t sma[];
    uint32_t* Qs = sma;
    const uint32_t sbase = smem_u32(sma);

    const int tq = blockIdx.x * 128;
    const int b = blockIdx.y >> 4;
    const int h = blockIdx.y & 15;
    const int tid = threadIdx.x;
    const int w = tid >> 5;
    const int lane = tid & 31;
    const int g = lane >> 2;
    const int tig = lane & 3;

    // fill Q tile pre-scaled by 0.125*log2(e) -> scores land in exp2 domain
    {
        const __half* Qg = g_QKVh + (size_t)(b * T_SEQ + tq) * E3 + h * HD;
        for (int it = tid; it < 128 * 16; it += 256) {
            int r = it >> 4, c4 = (it & 15) * 4;
            uint2 raw = *(const uint2*)(Qg + (size_t)r * E3 + c4);
            float2 f0 = __half22float2(*(__half2*)&raw.x);
            float2 f1 = __half22float2(*(__half2*)&raw.y);
            __half2 h0 = __floats2half2_rn(f0.x * QSCALE_LOG2, f0.y * QSCALE_LOG2);
            __half2 h1 = __floats2half2_rn(f1.x * QSCALE_LOG2, f1.y * QSCALE_LOG2);
            uint32_t* d = Qs + r * APADU + (c4 >> 1);
            d[0] = *(uint32_t*)&h0;
            d[1] = *(uint32_t*)&h1;
        }
    }

    const __half* KgBase = g_QKVh + (size_t)(b * T_SEQ) * E3 + EMB + h * HD;
    const __half* VgBase = g_QKVh + (size_t)(b * T_SEQ) * E3 + 2 * EMB + h * HD;

    auto issue_kv = [&](int s) {
        const int buf = s % 3;
        const int kt = s << 6;
        const uint32_t kbase = sbase + (uint32_t)(128 * APADU + buf * AT_STAGE_UINTS) * 4;
        const uint32_t vbase = kbase + (uint32_t)(64 * APADU) * 4;
#pragma unroll
        for (int i = 0; i < 4; i++) {
            int idx = tid + 256 * i;
            int row = (idx >> 3) & 63;
            int chunk = idx & 7;
            int isV = idx >> 9;
            const __half* src = (isV ? VgBase : KgBase) + (size_t)(kt + row) * E3 + chunk * 8;
            uint32_t dst = (isV ? vbase : kbase) + (uint32_t)(row * APADU + chunk * 4) * 4;
            cp_async16(dst, src);
        }
        cp_commit();
    };

    issue_kv(0);
    issue_kv(1);
    __syncthreads();   // Qs visible

    uint32_t qf[4][4];
    {
        const uint32_t* base = Qs + (w * 16 + g) * APADU;
#pragma unroll
        for (int ks = 0; ks < 4; ks++) {
            qf[ks][0] = base[ks * 8 + tig];
            qf[ks][1] = base[8 * APADU + ks * 8 + tig];
            qf[ks][2] = base[ks * 8 + tig + 4];
            qf[ks][3] = base[8 * APADU + ks * 8 + tig + 4];
        }
    }

    float oacc[8][4];
#pragma unroll
    for (int nt = 0; nt < 8; nt++)
#pragma unroll
        for (int e = 0; e < 4; e++) oacc[nt][e] = 0.f;
    float mrow[2] = { -1e30f, -1e30f };
    float lrow[2] = { 0.f, 0.f };

    const uint8_t* mb = mask + (size_t)b * T_SEQ;
    const int NBLK = T_SEQ / 64;

    const int lm_quad = lane >> 3, lm_r = lane & 7;
    const int lm_row = (lm_quad & 1) * 8 + lm_r;
    const int lm_d   = (lm_quad >> 1) * 8;

    for (int s = 0; s < NBLK; s++) {
        asm volatile("cp.async.wait_group 1;" ::: "memory");
        __syncthreads();
        if (s + 2 < NBLK) issue_kv(s + 2);
        else cp_commit();

        const int buf = s % 3;
        const int kt = s << 6;
        const uint32_t* Ksb = sma + 128 * APADU + buf * AT_STAGE_UINTS;
        const uint32_t vsb_addr = sbase + (uint32_t)(128 * APADU + buf * AT_STAGE_UINTS + 64 * APADU) * 4;

        float sacc[8][4];
#pragma unroll
        for (int nt = 0; nt < 8; nt++)
#pragma unroll
            for (int e = 0; e < 4; e++) sacc[nt][e] = 0.f;

#pragma unroll
        for (int ks = 0; ks < 4; ks++) {
#pragma unroll
            for (int nt = 0; nt < 8; nt++) {
                uint32_t bf[2];
                const uint32_t* kp = Ksb + (nt * 8 + g) * APADU + ks * 8 + tig;
                bf[0] = kp[0];
                bf[1] = kp[4];
                mma_f16(sacc[nt], qf[ks], bf);
            }
        }

        // mask (branchless select; scale already folded into Q)
#pragma unroll
        for (int nt = 0; nt < 8; nt++) {
            bool m0 = mb[kt + nt * 8 + 2 * tig] != 0;
            bool m1 = mb[kt + nt * 8 + 2 * tig + 1] != 0;
            sacc[nt][0] = m0 ? -1e30f : sacc[nt][0];
            sacc[nt][1] = m1 ? -1e30f : sacc[nt][1];
            sacc[nt][2] = m0 ? -1e30f : sacc[nt][2];
            sacc[nt][3] = m1 ? -1e30f : sacc[nt][3];
        }

        // online softmax in exp2 domain (branchless, R11 structure)
#pragma unroll
        for (int half = 0; half < 2; half++) {
            float mx = -1e30f;
#pragma unroll
            for (int nt = 0; nt < 8; nt++) {
                mx = fmaxf(mx, sacc[nt][2 * half + 0]);
                mx = fmaxf(mx, sacc[nt][2 * half + 1]);
            }
            mx = fmaxf(mx, __shfl_xor_sync(0xffffffffu, mx, 1));
            mx = fmaxf(mx, __shfl_xor_sync(0xffffffffu, mx, 2));
            float mn = fmaxf(mrow[half], mx);
            float alpha = ex2(mrow[half] - mn);
            mrow[half] = mn;
            float rs = 0.f;
#pragma unroll
            for (int nt = 0; nt < 8; nt++) {
                float p0 = ex2(sacc[nt][2 * half + 0] - mn);
                float p1 = ex2(sacc[nt][2 * half + 1] - mn);
                rs += p0 + p1;
                __half2 ph = __floats2half2_rn(p0, p1);
                sacc[nt][2 * half] = __uint_as_float(*(uint32_t*)&ph);
            }
            rs += __shfl_xor_sync(0xffffffffu, rs, 1);
            rs += __shfl_xor_sync(0xffffffffu, rs, 2);
            lrow[half] = lrow[half] * alpha + rs;
#pragma unroll
            for (int nt = 0; nt < 8; nt++) {
                oacc[nt][2 * half + 0] *= alpha;
                oacc[nt][2 * half + 1] *= alpha;
            }
        }

        // O += P V : P from registers, V via ldmatrix.x4.trans
#pragma unroll
        for (int ks = 0; ks < 4; ks++) {
            uint32_t af[4];
            af[0] = __float_as_uint(sacc[2 * ks + 0][0]);
            af[1] = __float_as_uint(sacc[2 * ks + 0][2]);
            af[2] = __float_as_uint(sacc[2 * ks + 1][0]);
            af[3] = __float_as_uint(sacc[2 * ks + 1][2]);
#pragma unroll
            for (int np = 0; np < 4; np++) {
                int row = ks * 16 + lm_row;
                int d   = np * 16 + lm_d;
                uint32_t addr = vsb_addr + (uint32_t)(row * APADU + (d >> 1)) * 4;
                uint32_t r0, r1, r2, r3;
                ldmx4t(r0, r1, r2, r3, addr);
                uint32_t b0[2] = { r0, r1 };
                uint32_t b1[2] = { r2, r3 };
                mma_f16(oacc[2 * np + 0], af, b0);
                mma_f16(oacc[2 * np + 1], af, b1);
            }
        }
    }

#pragma unroll
    for (int half = 0; half < 2; half++) {
        float inv = 1.f / lrow[half];
        int r = tq + w * 16 + g + half * 8;
        __half* dst = g_ATTNh + (size_t)(b * T_SEQ + r) * EMB + h * HD;
#pragma unroll
        for (int nt = 0; nt < 8; nt++) {
            *(__half2*)(dst + nt * 8 + 2 * tig) =
                __floats2half2_rn(oacc[nt][2 * half + 0] * inv,
                                  oacc[nt][2 * half + 1] * inv);
        }
    }
}

// ---------------------------------------------------------------------------
// LayerNorm (E=1024), warp-shuffle reduction. Optional fp16 copy.
// ---------------------------------------------------------------------------
__global__ __launch_bounds__(256) void ln_kernel(
    const float* __restrict__ X, const float* __restrict__ gw,
    const float* __restrict__ bw, float* __restrict__ out,
    __half* __restrict__ out_h, int transposed)
{
    int m = blockIdx.x;
    float4 v = ((const float4*)(X + (size_t)m * EMB))[threadIdx.x];
    float s = v.x + v.y + v.z + v.w;
    float sq = v.x * v.x + v.y * v.y + v.z * v.z + v.w * v.w;

#pragma unroll
    for (int o = 16; o >= 1; o >>= 1) {
        s  += __shfl_xor_sync(0xffffffffu, s,  o);
        sq += __shfl_xor_sync(0xffffffffu, sq, o);
    }
    __shared__ float ws[8], wq[8];
    if ((threadIdx.x & 31) == 0) {
        ws[threadIdx.x >> 5] = s;
        wq[threadIdx.x >> 5] = sq;
    }
    __syncthreads();
    float ts = 0.f, tq = 0.f;
#pragma unroll
    for (int i = 0; i < 8; i++) { ts += ws[i]; tq += wq[i]; }

    float mu  = ts * (1.f / EMB);
    float var = tq * (1.f / EMB) - mu * mu;
    float inv = rsqrtf(var + 1e-5f);

    float4 g4 = ((const float4*)gw)[threadIdx.x];
    float4 b4 = ((const float4*)bw)[threadIdx.x];
    float4 o;
    o.x = (v.x - mu) * inv * g4.x + b4.x;
    o.y = (v.y - mu) * inv * g4.y + b4.y;
    o.z = (v.z - mu) * inv * g4.z + b4.z;
    o.w = (v.w - mu) * inv * g4.w + b4.w;

    size_t obase;
    if (transposed) {
        int b = m / T_SEQ, t = m % T_SEQ;
        obase = (size_t)t * B_SZ * EMB + (size_t)b * EMB;
    } else {
        obase = (size_t)m * EMB;
    }
    ((float4*)(out + obase))[threadIdx.x] = o;
    if (out_h) {
        __half2 h01 = __floats2half2_rn(o.x, o.y);
        __half2 h23 = __floats2half2_rn(o.z, o.w);
        uint2 u;
        u.x = *(uint32_t*)&h01;
        u.y = *(uint32_t*)&h23;
        ((uint2*)(out_h + (size_t)m * EMB))[threadIdx.x] = u;
    }
}

// ---------------------------------------------------------------------------
extern "C" void kernel_launch(void* const* d_in, const int* in_sizes, int n_in,
                              void* d_out, int out_size)
{
    const float*   state = (const float*)d_in[0];
    const uint8_t* mask  = (const uint8_t*)d_in[1];
    const float* q_w  = (const float*)d_in[2];
    const float* q_b  = (const float*)d_in[3];
    const float* k_w  = (const float*)d_in[4];
    const float* k_b  = (const float*)d_in[5];
    const float* v_w  = (const float*)d_in[6];
    const float* v_b  = (const float*)d_in[7];
    const float* out_w = (const float*)d_in[8];
    const float* out_b = (const float*)d_in[9];
    const float* ln1_g = (const float*)d_in[10];
    const float* ln1_b = (const float*)d_in[11];
    const float* fc1_w = (const float*)d_in[12];
    const float* fc1_b = (const float*)d_in[13];
    const float* fc2_w = (const float*)d_in[14];
    const float* fc2_b = (const float*)d_in[15];
    const float* ln2_g = (const float*)d_in[16];
    const float* ln2_b = (const float*)d_in[17];
    float* out = (float*)d_out;

    float *pX0, *pY, *pX1, *pBQKV;
    __half *pX0h, *pQKVh, *pATTNh, *pX1h, *pHh;
    __half *pWQKV, *pWO, *pW1, *pW2;
    cudaGetSymbolAddress((void**)&pX0,    g_X0);
    cudaGetSymbolAddress((void**)&pY,     g_Y);
    cudaGetSymbolAddress((void**)&pX1,    g_X1);
    cudaGetSymbolAddress((void**)&pX0h,   g_X0h);
    cudaGetSymbolAddress((void**)&pQKVh,  g_QKVh);
    cudaGetSymbolAddress((void**)&pATTNh, g_ATTNh);
    cudaGetSymbolAddress((void**)&pX1h,   g_X1h);
    cudaGetSymbolAddress((void**)&pHh,    g_Hh);
    cudaGetSymbolAddress((void**)&pWQKV,  g_WQKVh);
    cudaGetSymbolAddress((void**)&pBQKV,  g_BQKV);
    cudaGetSymbolAddress((void**)&pWO,    g_WOh);
    cudaGetSymbolAddress((void**)&pW1,    g_W1h);
    cudaGetSymbolAddress((void**)&pW2,    g_W2h);

    cudaFuncSetAttribute(attn_mma_kernel, cudaFuncAttributeMaxDynamicSharedMemorySize,
                         AT_SMEM_BYTES);
    cudaFuncSetAttribute(gemm_f16_kernel, cudaFuncAttributeMaxDynamicSharedMemorySize,
                         GEMM_SMEM_BYTES);

    // 0. prologue
    round_all_kernel<<<(12 * NW1 + E3) / 1024, 256>>>(q_w, k_w, v_w, out_w, fc1_w, fc2_w,
                                                      q_b, k_b, v_b);
    transpose_in_kernel<<<MTOK, 256>>>(state);

    // 1. fused QKV projection
    dim3 gQKV(E3 / 128, MTOK / 128);
    gemm_f16_kernel<<<gQKV, 256, GEMM_SMEM_BYTES>>>(pX0h, pWQKV, pBQKV, nullptr, nullptr, pQKVh, MTOK, E3, EMB, 0);

    // 2. attention
    dim3 gAttn(T_SEQ / 128, B_SZ * NHEADS);
    attn_mma_kernel<<<gAttn, 256, AT_SMEM_BYTES>>>(mask);

    // 3. out projection + residual(X0)
    dim3 gProj(EMB / 128, MTOK / 128);
    gemm_f16_kernel<<<gProj, 256, GEMM_SMEM_BYTES>>>(pATTNh, pWO, out_b, pX0, pY, nullptr, MTOK, EMB, EMB, 3);

    // 4. LN1
    ln_kernel<<<MTOK, 256>>>(pY, ln1_g, ln1_b, pX1, pX1h, 0);

    // 5. fc1 + relu
    dim3 gFc1(FFN_DIM / 128, MTOK / 128);
    gemm_f16_kernel<<<gFc1, 256, GEMM_SMEM_BYTES>>>(pX1h, pW1, fc1_b, nullptr, nullptr, pHh, MTOK, FFN_DIM, EMB, 2);

    // 6. fc2 + residual(X1)
    gemm_f16_kernel<<<gProj, 256, GEMM_SMEM_BYTES>>>(pHh, pW2, fc2_b, pX1, pY, nullptr, MTOK, EMB, FFN_DIM, 3);

    // 7. LN2 -> output (T,B,E)
    ln_kernel<<<MTOK, 256>>>(pY, ln2_g, ln2_b, out, nullptr, 1);
}

// round 17
// speedup vs baseline: 1.0486x; 1.0197x over previous
#include <cuda_runtime.h>
#include <cuda_fp16.h>
#include <math.h>
#include <stdint.h>

// Problem constants
#define T_SEQ 2048
#define B_SZ  4
#define EMB   1024
#define NHEADS 16
#define HD    64
#define FFN_DIM 4096
#define MTOK  (T_SEQ * B_SZ)   // 8192 tokens
#define E3    (3 * EMB)

// ---------------- scratch (device globals; no cudaMalloc allowed) ----------
__device__ float  g_X0 [MTOK * EMB];
__device__ float  g_Y  [MTOK * EMB];
__device__ float  g_X1 [MTOK * EMB];
__device__ __half g_X0h[MTOK * EMB];
__device__ __half g_QKVh[MTOK * E3];
__device__ __half g_ATTNh[MTOK * EMB];
__device__ __half g_X1h[MTOK * EMB];
__device__ __half g_Hh [MTOK * FFN_DIM];
__device__ __half g_WQKVh[E3 * EMB];
__device__ float  g_BQKV [E3];
__device__ __half g_WOh[EMB * EMB];
__device__ __half g_W1h[FFN_DIM * EMB];
__device__ __half g_W2h[EMB * FFN_DIM];

// ---------------------------------------------------------------------------
__device__ __forceinline__ uint32_t smem_u32(const void* p) {
    uint32_t a;
    asm("{ .reg .u64 t; cvta.to.shared.u64 t, %1; cvt.u32.u64 %0, t; }" : "=r"(a) : "l"(p));
    return a;
}
__device__ __forceinline__ void mma_f16(float* d, const uint32_t* a, const uint32_t* b) {
    asm volatile(
        "mma.sync.aligned.m16n8k16.row.col.f32.f16.f16.f32 "
        "{%0,%1,%2,%3}, {%4,%5,%6,%7}, {%8,%9}, {%0,%1,%2,%3};"
        : "+f"(d[0]), "+f"(d[1]), "+f"(d[2]), "+f"(d[3])
        : "r"(a[0]), "r"(a[1]), "r"(a[2]), "r"(a[3]), "r"(b[0]), "r"(b[1]));
}
__device__ __forceinline__ void ldmx4t(uint32_t& r0, uint32_t& r1, uint32_t& r2, uint32_t& r3,
                                       uint32_t a) {
    asm volatile("ldmatrix.sync.aligned.m8n8.x4.trans.shared.b16 {%0,%1,%2,%3}, [%4];"
                 : "=r"(r0), "=r"(r1), "=r"(r2), "=r"(r3) : "r"(a));
}
__device__ __forceinline__ void ldmx2t(uint32_t& r0, uint32_t& r1, uint32_t a) {
    asm volatile("ldmatrix.sync.aligned.m8n8.x2.trans.shared.b16 {%0,%1}, [%2];"
                 : "=r"(r0), "=r"(r1) : "r"(a));
}
__device__ __forceinline__ void cp_async16(uint32_t dst, const void* src) {
    asm volatile("cp.async.cg.shared.global [%0], [%1], 16;" :: "r"(dst), "l"(src));
}
__device__ __forceinline__ void cp_commit() { asm volatile("cp.async.commit_group;"); }
__device__ __forceinline__ float ex2(float x) {
    float r;
    asm("ex2.approx.f32 %0, %1;" : "=f"(r) : "f"(x));
    return r;
}
__device__ __forceinline__ uint32_t ex2_h2(uint32_t x) {
    uint32_t r;
    asm("ex2.approx.f16x2 %0, %1;" : "=r"(r) : "r"(x));
    return r;
}

// ---------------------------------------------------------------------------
// Round ALL weights fp32 -> fp16 + concat QKV biases, one launch.
// ---------------------------------------------------------------------------
#define NW1 (EMB * EMB)
__global__ __launch_bounds__(256) void round_all_kernel(
    const float* __restrict__ q_w, const float* __restrict__ k_w,
    const float* __restrict__ v_w, const float* __restrict__ out_w,
    const float* __restrict__ fc1_w, const float* __restrict__ fc2_w,
    const float* __restrict__ q_b, const float* __restrict__ k_b,
    const float* __restrict__ v_b)
{
    int i = (blockIdx.x * 256 + threadIdx.x) * 4;
    if (i >= 12 * NW1) {
        int j = i - 12 * NW1;
        if (j < E3) {
            const float* s = (j < EMB) ? q_b : (j < 2 * EMB) ? k_b : v_b;
            *(float4*)(g_BQKV + j) = *(const float4*)(s + (j & (EMB - 1)));
        }
        return;
    }
    const float* src;
    __half* dst;
    int off;
    if (i < 3 * NW1) {
        dst = g_WQKVh + i;
        if (i < NW1)          { src = q_w; off = i; }
        else if (i < 2 * NW1) { src = k_w; off = i - NW1; }
        else                  { src = v_w; off = i - 2 * NW1; }
    } else if (i < 4 * NW1) { dst = g_WOh + (i - 3 * NW1); src = out_w; off = i - 3 * NW1; }
    else if (i < 8 * NW1)   { dst = g_W1h + (i - 4 * NW1); src = fc1_w; off = i - 4 * NW1; }
    else                    { dst = g_W2h + (i - 8 * NW1); src = fc2_w; off = i - 8 * NW1; }
    float4 v = *(const float4*)(src + off);
    __half2 h01 = __floats2half2_rn(v.x, v.y);
    __half2 h23 = __floats2half2_rn(v.z, v.w);
    uint2 u;
    u.x = *(uint32_t*)&h01;
    u.y = *(uint32_t*)&h23;
    *(uint2*)dst = u;
}

// ---------------------------------------------------------------------------
// fp16 tensor-core GEMM (mma.sync m16n8k16), 3-stage cp.async ring. (R10 best)
// ---------------------------------------------------------------------------
#define GPAD 36
#define STG_OP_UINTS (128 * GPAD)
#define STG_UINTS    (2 * STG_OP_UINTS)
#define GEMM_SMEM_BYTES (3 * STG_UINTS * 4)   // 110592

__global__ __launch_bounds__(256, 2) void gemm_f16_kernel(
    const __half* __restrict__ A, const __half* __restrict__ W,
    const float* __restrict__ bias, const float* __restrict__ res,
    float* __restrict__ Cf, __half* __restrict__ Ch,
    int M, int N, int K, int mode)
{
    extern __shared__ uint32_t smg[];
    const uint32_t sbase = smem_u32(smg);

    const int tid = threadIdx.x;
    const int wid = tid >> 5;
    const int lane = tid & 31;
    const int g   = lane >> 2;
    const int tig = lane & 3;
    const int wm = wid >> 2;
    const int wn = wid & 3;
    const int m0 = blockIdx.y * 128;
    const int n0 = blockIdx.x * 128;

    const __half* Ap = A + (size_t)m0 * K;
    const __half* Wp = W + (size_t)n0 * K;

    float acc[4][4][4];
#pragma unroll
    for (int mt = 0; mt < 4; mt++)
#pragma unroll
        for (int nt = 0; nt < 4; nt++)
#pragma unroll
            for (int e = 0; e < 4; e++) acc[mt][nt][e] = 0.f;

    const int S = K >> 6;

    auto issue_stage = [&](int s) {
        const int buf = s % 3;
        const int k0h = s << 6;
        const uint32_t abase = sbase + (uint32_t)(buf * STG_UINTS) * 4;
        const uint32_t bbase = abase + STG_OP_UINTS * 4;
#pragma unroll
        for (int i = 0; i < 4; i++) {
            int idx = tid + 256 * i;
            int row = idx >> 3, cu = (idx & 7) << 2;
            cp_async16(abase + (uint32_t)(row * GPAD + cu) * 4,
                       Ap + (size_t)row * K + k0h + cu * 2);
            cp_async16(bbase + (uint32_t)(row * GPAD + cu) * 4,
                       Wp + (size_t)row * K + k0h + cu * 2);
        }
        cp_commit();
    };

    issue_stage(0);
    issue_stage(1);

    for (int s = 0; s < S; s++) {
        asm volatile("cp.async.wait_group 1;" ::: "memory");
        __syncthreads();
        if (s + 2 < S) issue_stage(s + 2);
        else cp_commit();

        const int buf = s % 3;
        const uint32_t* Ab = smg + buf * STG_UINTS + (wm * 64) * GPAD;
        const uint32_t* Bb = smg + buf * STG_UINTS + STG_OP_UINTS + (wn * 32) * GPAD;
#pragma unroll
        for (int ks = 0; ks < 4; ks++) {
            uint32_t bf[4][2];
#pragma unroll
            for (int nt = 0; nt < 4; nt++) {
                const uint32_t* bp = Bb + (nt * 8 + g) * GPAD + ks * 8 + tig;
                bf[nt][0] = bp[0];
                bf[nt][1] = bp[4];
            }
#pragma unroll
            for (int mt = 0; mt < 4; mt++) {
                uint32_t af[4];
                const uint32_t* ap = Ab + (mt * 16 + g) * GPAD + ks * 8 + tig;
                af[0] = ap[0];
                af[1] = ap[8 * GPAD];
                af[2] = ap[4];
                af[3] = ap[8 * GPAD + 4];
#pragma unroll
                for (int nt = 0; nt < 4; nt++)
                    mma_f16(acc[mt][nt], af, bf[nt]);
            }
        }
    }

#pragma unroll
    for (int mt = 0; mt < 4; mt++) {
        int r0 = m0 + wm * 64 + mt * 16 + g;
#pragma unroll
        for (int half = 0; half < 2; half++) {
            int m = r0 + half * 8;
#pragma unroll
            for (int nt = 0; nt < 4; nt++) {
                int n = wn * 32 + nt * 8 + tig * 2;
                float ox = acc[mt][nt][half * 2 + 0] + bias[n0 + n + 0];
                float oy = acc[mt][nt][half * 2 + 1] + bias[n0 + n + 1];
                if (mode == 3) {
                    const float* Rrow = res + (size_t)m * N + n0;
                    float2 rr = *(const float2*)(Rrow + n);
                    *(float2*)(Cf + (size_t)m * N + n0 + n) = make_float2(ox + rr.x, oy + rr.y);
                } else {
                    if (mode == 2) { ox = fmaxf(ox, 0.f); oy = fmaxf(oy, 0.f); }
                    *(__half2*)(Ch + (size_t)m * N + n0 + n) = __floats2half2_rn(ox, oy);
                }
            }
        }
    }
}

// ---------------------------------------------------------------------------
// Transpose (T,B,E) -> (B,T,E): exact fp32 + fp16 copy
// ---------------------------------------------------------------------------
__global__ __launch_bounds__(256) void transpose_in_kernel(const float* __restrict__ state)
{
    int m = blockIdx.x;
    int b = m / T_SEQ;
    int t = m % T_SEQ;
    float4 v = ((const float4*)(state + (size_t)t * B_SZ * EMB + (size_t)b * EMB))[threadIdx.x];
    ((float4*)(g_X0 + (size_t)m * EMB))[threadIdx.x] = v;
    __half2 h01 = __floats2half2_rn(v.x, v.y);
    __half2 h23 = __floats2half2_rn(v.z, v.w);
    uint2 u;
    u.x = *(uint32_t*)&h01;
    u.y = *(uint32_t*)&h23;
    ((uint2*)(g_X0h + (size_t)m * EMB))[threadIdx.x] = u;
}

// ---------------------------------------------------------------------------
// Flash attention: fp16 mma, register-resident P (computed via ex2.f16x2),
// row-sums accumulated FREE via a ones-column in V's smem pad (9th n-tile),
// log2-domain softmax, 3-stage cp.async KV ring, one sync per kv-block.
// ---------------------------------------------------------------------------
#define APADU 36
#define AT_STAGE_UINTS (2 * 64 * APADU)
#define AT_SMEM_BYTES ((128 * APADU + 3 * AT_STAGE_UINTS) * 4)   // 73728
#define QSCALE_LOG2 (0.125f * 1.4426950408889634f)   // (1/sqrt(64)) * log2(e)

__global__ __launch_bounds__(256, 2) void attn_mma_kernel(const uint8_t* __restrict__ mask)
{
    extern __shared__ uint32_t sma[];
    uint32_t* Qs = sma;
    const uint32_t sbase = smem_u32(sma);

    const int tq = blockIdx.x * 128;
    const int b = blockIdx.y >> 4;
    const int h = blockIdx.y & 15;
    const int tid = threadIdx.x;
    const int w = tid >> 5;
    const int lane = tid & 31;
    const int g = lane >> 2;
    const int tig = lane & 3;

    // fill Q tile pre-scaled by 0.125*log2(e) -> scores land in exp2 domain
    {
        const __half* Qg = g_QKVh + (size_t)(b * T_SEQ + tq) * E3 + h * HD;
        for (int it = tid; it < 128 * 16; it += 256) {
            int r = it >> 4, c4 = (it & 15) * 4;
            uint2 raw = *(const uint2*)(Qg + (size_t)r * E3 + c4);
            float2 f0 = __half22float2(*(__half2*)&raw.x);
            float2 f1 = __half22float2(*(__half2*)&raw.y);
            __half2 h0 = __floats2half2_rn(f0.x * QSCALE_LOG2, f0.y * QSCALE_LOG2);
            __half2 h1 = __floats2half2_rn(f1.x * QSCALE_LOG2, f1.y * QSCALE_LOG2);
            uint32_t* d = Qs + r * APADU + (c4 >> 1);
            d[0] = *(uint32_t*)&h0;
            d[1] = *(uint32_t*)&h1;
        }
    }

    // init the ones-column in V pad (uints 32..35 of each V row, all 3 stages)
    // cp.async only writes uints 0..31, so this persists across the ring.
    for (int i = tid; i < 3 * 64; i += 256) {
        int stg = i >> 6, row = i & 63;
        uint32_t* p = sma + 128 * APADU + stg * AT_STAGE_UINTS + 64 * APADU + row * APADU + 32;
        p[0] = 0x00003C00u;   // (half)1.0 in low, 0 in high -> col 64 = 1, col 65 = 0
        p[1] = 0u; p[2] = 0u; p[3] = 0u;   // cols 66..71 = 0
    }

    const __half* KgBase = g_QKVh + (size_t)(b * T_SEQ) * E3 + EMB + h * HD;
    const __half* VgBase = g_QKVh + (size_t)(b * T_SEQ) * E3 + 2 * EMB + h * HD;

    auto issue_kv = [&](int s) {
        const int buf = s % 3;
        const int kt = s << 6;
        const uint32_t kbase = sbase + (uint32_t)(128 * APADU + buf * AT_STAGE_UINTS) * 4;
        const uint32_t vbase = kbase + (uint32_t)(64 * APADU) * 4;
#pragma unroll
        for (int i = 0; i < 4; i++) {
            int idx = tid + 256 * i;
            int row = (idx >> 3) & 63;
            int chunk = idx & 7;
            int isV = idx >> 9;
            const __half* src = (isV ? VgBase : KgBase) + (size_t)(kt + row) * E3 + chunk * 8;
            uint32_t dst = (isV ? vbase : kbase) + (uint32_t)(row * APADU + chunk * 4) * 4;
            cp_async16(dst, src);
        }
        cp_commit();
    };

    issue_kv(0);
    issue_kv(1);
    __syncthreads();   // Qs + pad-init visible

    uint32_t qf[4][4];
    {
        const uint32_t* base = Qs + (w * 16 + g) * APADU;
#pragma unroll
        for (int ks = 0; ks < 4; ks++) {
            qf[ks][0] = base[ks * 8 + tig];
            qf[ks][1] = base[8 * APADU + ks * 8 + tig];
            qf[ks][2] = base[ks * 8 + tig + 4];
            qf[ks][3] = base[8 * APADU + ks * 8 + tig + 4];
        }
    }

    float oacc[8][4];
#pragma unroll
    for (int nt = 0; nt < 8; nt++)
#pragma unroll
        for (int e = 0; e < 4; e++) oacc[nt][e] = 0.f;
    float osum[4] = { 0.f, 0.f, 0.f, 0.f };   // 9th n-tile: col 0 = row sums of P
    float mrow[2] = { -1e30f, -1e30f };

    const uint8_t* mb = mask + (size_t)b * T_SEQ;
    const int NBLK = T_SEQ / 64;

    const int lm_quad = lane >> 3, lm_r = lane & 7;
    const int lm_row = (lm_quad & 1) * 8 + lm_r;
    const int lm_d   = (lm_quad >> 1) * 8;
    const int lm2_row = lane & 15;            // x2 trans: lanes 0..15 -> k rows

    for (int s = 0; s < NBLK; s++) {
        asm volatile("cp.async.wait_group 1;" ::: "memory");
        __syncthreads();
        if (s + 2 < NBLK) issue_kv(s + 2);
        else cp_commit();

        const int buf = s % 3;
        const int kt = s << 6;
        const uint32_t* Ksb = sma + 128 * APADU + buf * AT_STAGE_UINTS;
        const uint32_t vsb_addr = sbase + (uint32_t)(128 * APADU + buf * AT_STAGE_UINTS + 64 * APADU) * 4;

        float sacc[8][4];
#pragma unroll
        for (int nt = 0; nt < 8; nt++)
#pragma unroll
            for (int e = 0; e < 4; e++) sacc[nt][e] = 0.f;

#pragma unroll
        for (int ks = 0; ks < 4; ks++) {
#pragma unroll
            for (int nt = 0; nt < 8; nt++) {
                uint32_t bf[2];
                const uint32_t* kp = Ksb + (nt * 8 + g) * APADU + ks * 8 + tig;
                bf[0] = kp[0];
                bf[1] = kp[4];
                mma_f16(sacc[nt], qf[ks], bf);
            }
        }

        // mask (branchless select; scale already folded into Q)
#pragma unroll
        for (int nt = 0; nt < 8; nt++) {
            bool m0 = mb[kt + nt * 8 + 2 * tig] != 0;
            bool m1 = mb[kt + nt * 8 + 2 * tig + 1] != 0;
            sacc[nt][0] = m0 ? -1e30f : sacc[nt][0];
            sacc[nt][1] = m1 ? -1e30f : sacc[nt][1];
            sacc[nt][2] = m0 ? -1e30f : sacc[nt][2];
            sacc[nt][3] = m1 ? -1e30f : sacc[nt][3];
        }

        // online softmax in exp2 domain; P computed in half2 via ex2.f16x2,
        // packed into sacc[nt][2*half]. No rs computation (ones-column).
#pragma unroll
        for (int half = 0; half < 2; half++) {
            float mx = -1e30f;
#pragma unroll
            for (int nt = 0; nt < 8; nt++) {
                mx = fmaxf(mx, sacc[nt][2 * half + 0]);
                mx = fmaxf(mx, sacc[nt][2 * half + 1]);
            }
            mx = fmaxf(mx, __shfl_xor_sync(0xffffffffu, mx, 1));
            mx = fmaxf(mx, __shfl_xor_sync(0xffffffffu, mx, 2));
            float mn = fmaxf(mrow[half], mx);
            float alpha = ex2(mrow[half] - mn);
            mrow[half] = mn;
#pragma unroll
            for (int nt = 0; nt < 8; nt++) {
                __half2 sh = __floats2half2_rn(sacc[nt][2 * half + 0] - mn,
                                               sacc[nt][2 * half + 1] - mn);
                sacc[nt][2 * half] = __uint_as_float(ex2_h2(*(uint32_t*)&sh));
            }
#pragma unroll
            for (int nt = 0; nt < 8; nt++) {
                oacc[nt][2 * half + 0] *= alpha;
                oacc[nt][2 * half + 1] *= alpha;
            }
            osum[2 * half + 0] *= alpha;
            osum[2 * half + 1] *= alpha;
        }

        // O += P V (8 tiles) + row-sum tile (9th, ones-column in V pad)
#pragma unroll
        for (int ks = 0; ks < 4; ks++) {
            uint32_t af[4];
            af[0] = __float_as_uint(sacc[2 * ks + 0][0]);
            af[1] = __float_as_uint(sacc[2 * ks + 0][2]);
            af[2] = __float_as_uint(sacc[2 * ks + 1][0]);
            af[3] = __float_as_uint(sacc[2 * ks + 1][2]);
#pragma unroll
            for (int np = 0; np < 4; np++) {
                int row = ks * 16 + lm_row;
                int d   = np * 16 + lm_d;
                uint32_t addr = vsb_addr + (uint32_t)(row * APADU + (d >> 1)) * 4;
                uint32_t r0, r1, r2, r3;
                ldmx4t(r0, r1, r2, r3, addr);
                uint32_t b0[2] = { r0, r1 };
                uint32_t b1[2] = { r2, r3 };
                mma_f16(oacc[2 * np + 0], af, b0);
                mma_f16(oacc[2 * np + 1], af, b1);
            }
            // 9th tile: cols 64..71 (uints 32..35 = pad; col 64 = ones)
            {
                uint32_t addr9 = vsb_addr + (uint32_t)((ks * 16 + lm2_row) * APADU + 32) * 4;
                uint32_t r0, r1;
                ldmx2t(r0, r1, addr9);
                uint32_t b9[2] = { r0, r1 };
                mma_f16(osum, af, b9);
            }
        }
    }

    // row sums live at tig=0 lanes (col 64 of the 9th tile): broadcast
    float lsum0 = __shfl_sync(0xffffffffu, osum[0], lane & ~3);
    float lsum1 = __shfl_sync(0xffffffffu, osum[2], lane & ~3);

#pragma unroll
    for (int half = 0; half < 2; half++) {
        float inv = 1.f / (half ? lsum1 : lsum0);
        int r = tq + w * 16 + g + half * 8;
        __half* dst = g_ATTNh + (size_t)(b * T_SEQ + r) * EMB + h * HD;
#pragma unroll
        for (int nt = 0; nt < 8; nt++) {
            *(__half2*)(dst + nt * 8 + 2 * tig) =
                __floats2half2_rn(oacc[nt][2 * half + 0] * inv,
                                  oacc[nt][2 * half + 1] * inv);
        }
    }
}

// ---------------------------------------------------------------------------
// LayerNorm (E=1024), warp-shuffle reduction. Optional fp16 copy.
// ---------------------------------------------------------------------------
__global__ __launch_bounds__(256) void ln_kernel(
    const float* __restrict__ X, const float* __restrict__ gw,
    const float* __restrict__ bw, float* __restrict__ out,
    __half* __restrict__ out_h, int transposed)
{
    int m = blockIdx.x;
    float4 v = ((const float4*)(X + (size_t)m * EMB))[threadIdx.x];
    float s = v.x + v.y + v.z + v.w;
    float sq = v.x * v.x + v.y * v.y + v.z * v.z + v.w * v.w;

#pragma unroll
    for (int o = 16; o >= 1; o >>= 1) {
        s  += __shfl_xor_sync(0xffffffffu, s,  o);
        sq += __shfl_xor_sync(0xffffffffu, sq, o);
    }
    __shared__ float ws[8], wq[8];
    if ((threadIdx.x & 31) == 0) {
        ws[threadIdx.x >> 5] = s;
        wq[threadIdx.x >> 5] = sq;
    }
    __syncthreads();
    float ts = 0.f, tq = 0.f;
#pragma unroll
    for (int i = 0; i < 8; i++) { ts += ws[i]; tq += wq[i]; }

    float mu  = ts * (1.f / EMB);
    float var = tq * (1.f / EMB) - mu * mu;
    float inv = rsqrtf(var + 1e-5f);

    float4 g4 = ((const float4*)gw)[threadIdx.x];
    float4 b4 = ((const float4*)bw)[threadIdx.x];
    float4 o;
    o.x = (v.x - mu) * inv * g4.x + b4.x;
    o.y = (v.y - mu) * inv * g4.y + b4.y;
    o.z = (v.z - mu) * inv * g4.z + b4.z;
    o.w = (v.w - mu) * inv * g4.w + b4.w;

    size_t obase;
    if (transposed) {
        int b = m / T_SEQ, t = m % T_SEQ;
        obase = (size_t)t * B_SZ * EMB + (size_t)b * EMB;
    } else {
        obase = (size_t)m * EMB;
    }
    ((float4*)(out + obase))[threadIdx.x] = o;
    if (out_h) {
        __half2 h01 = __floats2half2_rn(o.x, o.y);
        __half2 h23 = __floats2half2_rn(o.z, o.w);
        uint2 u;
        u.x = *(uint32_t*)&h01;
        u.y = *(uint32_t*)&h23;
        ((uint2*)(out_h + (size_t)m * EMB))[threadIdx.x] = u;
    }
}

// ---------------------------------------------------------------------------
extern "C" void kernel_launch(void* const* d_in, const int* in_sizes, int n_in,
                              void* d_out, int out_size)
{
    const float*   state = (const float*)d_in[0];
    const uint8_t* mask  = (const uint8_t*)d_in[1];
    const float* q_w  = (const float*)d_in[2];
    const float* q_b  = (const float*)d_in[3];
    const float* k_w  = (const float*)d_in[4];
    const float* k_b  = (const float*)d_in[5];
    const float* v_w  = (const float*)d_in[6];
    const float* v_b  = (const float*)d_in[7];
    const float* out_w = (const float*)d_in[8];
    const float* out_b = (const float*)d_in[9];
    const float* ln1_g = (const float*)d_in[10];
    const float* ln1_b = (const float*)d_in[11];
    const float* fc1_w = (const float*)d_in[12];
    const float* fc1_b = (const float*)d_in[13];
    const float* fc2_w = (const float*)d_in[14];
    const float* fc2_b = (const float*)d_in[15];
    const float* ln2_g = (const float*)d_in[16];
    const float* ln2_b = (const float*)d_in[17];
    float* out = (float*)d_out;

    float *pX0, *pY, *pX1, *pBQKV;
    __half *pX0h, *pQKVh, *pATTNh, *pX1h, *pHh;
    __half *pWQKV, *pWO, *pW1, *pW2;
    cudaGetSymbolAddress((void**)&pX0,    g_X0);
    cudaGetSymbolAddress((void**)&pY,     g_Y);
    cudaGetSymbolAddress((void**)&pX1,    g_X1);
    cudaGetSymbolAddress((void**)&pX0h,   g_X0h);
    cudaGetSymbolAddress((void**)&pQKVh,  g_QKVh);
    cudaGetSymbolAddress((void**)&pATTNh, g_ATTNh);
    cudaGetSymbolAddress((void**)&pX1h,   g_X1h);
    cudaGetSymbolAddress((void**)&pHh,    g_Hh);
    cudaGetSymbolAddress((void**)&pWQKV,  g_WQKVh);
    cudaGetSymbolAddress((void**)&pBQKV,  g_BQKV);
    cudaGetSymbolAddress((void**)&pWO,    g_WOh);
    cudaGetSymbolAddress((void**)&pW1,    g_W1h);
    cudaGetSymbolAddress((void**)&pW2,    g_W2h);

    cudaFuncSetAttribute(attn_mma_kernel, cudaFuncAttributeMaxDynamicSharedMemorySize,
                         AT_SMEM_BYTES);
    cudaFuncSetAttribute(gemm_f16_kernel, cudaFuncAttributeMaxDynamicSharedMemorySize,
                         GEMM_SMEM_BYTES);

    // 0. prologue
    round_all_kernel<<<(12 * NW1 + E3) / 1024, 256>>>(q_w, k_w, v_w, out_w, fc1_w, fc2_w,
                                                      q_b, k_b, v_b);
    transpose_in_kernel<<<MTOK, 256>>>(state);

    // 1. fused QKV projection
    dim3 gQKV(E3 / 128, MTOK / 128);
    gemm_f16_kernel<<<gQKV, 256, GEMM_SMEM_BYTES>>>(pX0h, pWQKV, pBQKV, nullptr, nullptr, pQKVh, MTOK, E3, EMB, 0);

    // 2. attention
    dim3 gAttn(T_SEQ / 128, B_SZ * NHEADS);
    attn_mma_kernel<<<gAttn, 256, AT_SMEM_BYTES>>>(mask);

    // 3. out projection + residual(X0)
    dim3 gProj(EMB / 128, MTOK / 128);
    gemm_f16_kernel<<<gProj, 256, GEMM_SMEM_BYTES>>>(pATTNh, pWO, out_b, pX0, pY, nullptr, MTOK, EMB, EMB, 3);

    // 4. LN1
    ln_kernel<<<MTOK, 256>>>(pY, ln1_g, ln1_b, pX1, pX1h, 0);

    // 5. fc1 + relu
    dim3 gFc1(FFN_DIM / 128, MTOK / 128);
    gemm_f16_kernel<<<gFc1, 256, GEMM_SMEM_BYTES>>>(pX1h, pW1, fc1_b, nullptr, nullptr, pHh, MTOK, FFN_DIM, EMB, 2);

    // 6. fc2 + residual(X1)
    gemm_f16_kernel<<<gProj, 256, GEMM_SMEM_BYTES>>>(pHh, pW2, fc2_b, pX1, pY, nullptr, MTOK, EMB, FFN_DIM, 3);

    // 7. LN2 -> output (T,B,E)
    ln_kernel<<<MTOK, 256>>>(pY, ln2_g, ln2_b, out, nullptr, 1);
}